// round 10
// baseline (speedup 1.0000x reference)
#include <cuda_runtime.h>
#include <cuda_fp16.h>
#include <math.h>
#include <stdint.h>

typedef unsigned long long ull;

#define HID   512
#define FOURH 2048
#define MID   256
#define CONDD 256
#define OPD   32
#define EXD   32
#define LLV   16
#define NN    1024
#define TT    8
#define BB    (LLV*NN)   /* 16384 */

// ---------------------------------------------------------------- scratch ---
__device__ __align__(16) __half g_cond16[(size_t)BB*2048];
__device__ __align__(16) __half g_h1a[(size_t)BB*HID];
__device__ __align__(16) __half g_h1b[(size_t)BB*HID];
__device__ __align__(16) float  g_c1[(size_t)BB*HID];
__device__ __align__(16) float  g_last[(size_t)BB*MID];
__device__ __align__(16) __half g_last16[(size_t)BB*MID];
__device__ __align__(16) __half g_opex16[(size_t)BB*64];
__device__ __align__(16) float  g_xp2[(size_t)BB*FOURH];
__device__ __align__(16) float  g_h2[NN*HID];
__device__ __align__(16) float  g_c2[NN*HID];
__device__ __align__(16) __half g_hb16[NN*HID];
__device__ __align__(16) float  g_cb[NN*HID];
__device__ __align__(16) __half g_w1h[FOURH*768];
__device__ __align__(16) __half g_w1l[FOURH*768];
__device__ __align__(16) __half g_cwh[MID*HID];
__device__ __align__(16) __half g_cwl[MID*HID];
__device__ __align__(16) __half g_w2ih[FOURH*320];
__device__ __align__(16) __half g_w2il[FOURH*320];
__device__ __align__(16) __half g_w2hh[FOURH*HID];
__device__ __align__(16) __half g_w2hl[FOURH*HID];
__device__ double g_bnacc[2*HID];
__device__ float  g_mu[HID];
__device__ float  g_rs[HID];
__device__ int    g_map64;

// ---------------------------------------------------------------- helpers ---
__device__ __forceinline__ uint32_t smem_u32(const void* p) {
    uint32_t a;
    asm("{ .reg .u64 t; cvta.to.shared.u64 t, %1; cvt.u32.u64 %0, t; }" : "=r"(a) : "l"(p));
    return a;
}
__device__ __forceinline__ void cpa16(uint32_t dst, const void* src) {
    asm volatile("cp.async.cg.shared.global [%0], [%1], 16;" :: "r"(dst), "l"(src) : "memory");
}
__device__ __forceinline__ void ldmx4(uint32_t* r, uint32_t addr) {
    asm volatile("ldmatrix.sync.aligned.m8n8.x4.shared.b16 {%0,%1,%2,%3}, [%4];"
        : "=r"(r[0]), "=r"(r[1]), "=r"(r[2]), "=r"(r[3]) : "r"(addr));
}
__device__ __forceinline__ void mma_f16(float* d, const uint32_t* a, const uint32_t* b) {
    asm volatile("mma.sync.aligned.m16n8k16.row.col.f32.f16.f16.f32 "
        "{%0,%1,%2,%3}, {%4,%5,%6,%7}, {%8,%9}, {%0,%1,%2,%3};"
        : "+f"(d[0]), "+f"(d[1]), "+f"(d[2]), "+f"(d[3])
        : "r"(a[0]), "r"(a[1]), "r"(a[2]), "r"(a[3]), "r"(b[0]), "r"(b[1]));
}
__device__ __forceinline__ float sigm(float x) { return 1.f / (1.f + expf(-x)); }

// ---------------------------------------------------------------- GEMM ------
// C[M,Nf] = A[M,K] @ B[Nf,K]^T, A fp16, B fp16 hi (+ lo product only for
// K-chunks with kc >= loFrom — the recurrent-weight region).
// CTA 128x128, K-chunk 32, TRIPLE-buffered cp.async, 80B-padded smem rows.
// MODE 0: fused LSTM cell (interleaved gates), c in-place, h->f16 out
// MODE 1: relu(+bias0) -> f32 C
// MODE 2: +bias0 (perm-indexed, interleaved C) -> f32 C
// MODE 3: fused LSTM cell + Cadd(xp2), c: cIn2->cIO, h->f32 out
#define T_BH 10240
#define T_BL 20480
#define STAGE 30720
#define SMEM_TOT (3*STAGE)

template<int MODE>
__global__ __launch_bounds__(256, 2)
void gemm_k(const __half* __restrict__ A0, long sA0, int kSplit,
            const __half* __restrict__ A1, long sA1,
            const __half* __restrict__ Bh, const __half* __restrict__ Bl,
            int loFrom,
            const float* __restrict__ bias0, const float* __restrict__ bias1,
            const float* __restrict__ Cadd,
            float* __restrict__ cIO, const float* __restrict__ cIn2,
            __half* __restrict__ hOutH, float* __restrict__ hOutF,
            int Nf, int K)
{
    extern __shared__ __align__(128) char sm[];
    uint32_t smb = smem_u32(sm);
    int tid = threadIdx.x;
    int mBase = blockIdx.y * 128;
    int nBase = blockIdx.x * 128;

    float acc[4][4][4];
#pragma unroll
    for (int a = 0; a < 4; a++)
#pragma unroll
        for (int b = 0; b < 4; b++)
#pragma unroll
            for (int q = 0; q < 4; q++) acc[a][b][q] = 0.f;

    int NC = K >> 5;   // always >= 10 for our shapes

    auto issue_stage = [&](int s, int c) {
        int kc = c << 5;
        const __half* ap; long sA; int col;
        if (kc < kSplit) { ap = A0; sA = sA0; col = kc; }
        else             { ap = A1; sA = sA1; col = kc - kSplit; }
        uint32_t stg = smb + (uint32_t)s * STAGE;
#pragma unroll
        for (int i = 0; i < 2; i++) {
            int idx = tid + (i << 8);
            int row = idx >> 2, cc = idx & 3;
            long eo = (long)(mBase + row) * sA + col + (cc << 3);
            cpa16(stg + row * 80 + cc * 16, ap + eo);
        }
        int lo = (kc >= loFrom);
#pragma unroll
        for (int i = 0; i < 2; i++) {
            int idx = tid + (i << 8);
            int row = idx >> 2, cc = idx & 3;
            long eo = (long)(nBase + row) * (long)K + kc + (cc << 3);
            uint32_t d = stg + row * 80 + cc * 16;
            cpa16(d + T_BH, Bh + eo);
            if (lo) cpa16(d + T_BL, Bl + eo);
        }
        asm volatile("cp.async.commit_group;" ::: "memory");
    };

    int lane = tid & 31, wid = tid >> 5;
    int wm = wid & 1, wn = wid >> 1;
    int arow = (lane & 7) + (((lane >> 3) & 1) << 3);
    int ahalf = lane >> 4;
    int brow = ((lane >> 4) << 3) + (lane & 7);
    int bhalf = (lane >> 3) & 1;

    issue_stage(0, 0);
    issue_stage(1, 1);
    for (int c = 0; c < NC; c++) {
        if (c + 2 < NC) {
            issue_stage((c + 2) % 3, c + 2);
            asm volatile("cp.async.wait_group 2;" ::: "memory");
        } else if (c + 1 < NC) {
            asm volatile("cp.async.wait_group 1;" ::: "memory");
        } else {
            asm volatile("cp.async.wait_group 0;" ::: "memory");
        }
        __syncthreads();

        uint32_t sb = smb + (uint32_t)(c % 3) * STAGE;
        int lo = ((c << 5) >= loFrom);
#pragma unroll
        for (int ks = 0; ks < 2; ks++) {
            uint32_t a_r[4][4], b_h[4][2], b_l[4][2];
#pragma unroll
            for (int mt = 0; mt < 4; mt++) {
                uint32_t ad = sb + (uint32_t)(wm * 64 + mt * 16 + arow) * 80
                            + (uint32_t)(ks * 2 + ahalf) * 16;
                ldmx4(a_r[mt], ad);
            }
#pragma unroll
            for (int bp = 0; bp < 2; bp++) {
                uint32_t bd = sb + T_BH + (uint32_t)(wn * 32 + bp * 16 + brow) * 80
                            + (uint32_t)(ks * 2 + bhalf) * 16;
                ldmx4(&b_h[bp * 2][0], bd);
                if (lo) ldmx4(&b_l[bp * 2][0], bd + (T_BL - T_BH));
            }
            if (lo) {
#pragma unroll
                for (int mt = 0; mt < 4; mt++)
#pragma unroll
                    for (int nt = 0; nt < 4; nt++) {
                        mma_f16(acc[mt][nt], a_r[mt], b_h[nt]);
                        mma_f16(acc[mt][nt], a_r[mt], b_l[nt]);
                    }
            } else {
#pragma unroll
                for (int mt = 0; mt < 4; mt++)
#pragma unroll
                    for (int nt = 0; nt < 4; nt++)
                        mma_f16(acc[mt][nt], a_r[mt], b_h[nt]);
            }
        }
        __syncthreads();
    }

    // ---- epilogue
    if (MODE == 1 || MODE == 2) {
        int r4 = lane >> 2, c2 = (lane & 3) << 1;
#pragma unroll
        for (int mt = 0; mt < 4; mt++) {
            long m0 = mBase + wm * 64 + mt * 16 + r4;
#pragma unroll
            for (int nt = 0; nt < 4; nt++) {
                int gn = nBase + wn * 32 + nt * 8 + c2;
                int bx = (MODE == 2) ? ((gn & 3) * 512 + (gn >> 2)) : gn;
                int by = (MODE == 2) ? (((gn + 1) & 3) * 512 + ((gn + 1) >> 2)) : gn + 1;
                float b0x = bias0[bx], b0y = bias0[by];
#pragma unroll
                for (int hf = 0; hf < 2; hf++) {
                    long gm = m0 + hf * 8;
                    float vx = acc[mt][nt][hf * 2 + 0] + b0x;
                    float vy = acc[mt][nt][hf * 2 + 1] + b0y;
                    if (MODE == 1) { vx = fmaxf(vx, 0.f); vy = fmaxf(vy, 0.f); }
                    float2 v; v.x = vx; v.y = vy;
                    *(float2*)&hOutF[gm * (long)Nf + gn] = v;
                }
            }
        }
    } else {
        int half = lane & 1, r4 = lane >> 2;
#pragma unroll
        for (int nt = 0; nt < 4; nt++) {
            int j = (nBase + wn * 32 + nt * 8 + ((lane & 2) << 1)) >> 2;
            float bi = bias0[j], bf = bias0[512 + j], bg = bias0[1024 + j], bo = bias0[1536 + j];
            if (MODE == 0) {
                bi += bias1[j]; bf += bias1[512 + j];
                bg += bias1[1024 + j]; bo += bias1[1536 + j];
            }
#pragma unroll
            for (int mt = 0; mt < 4; mt++) {
                float v0 = acc[mt][nt][0], v1 = acc[mt][nt][1];
                float v2 = acc[mt][nt][2], v3 = acc[mt][nt][3];
                float p0 = __shfl_xor_sync(0xFFFFFFFFu, v0, 1);
                float p1 = __shfl_xor_sync(0xFFFFFFFFu, v1, 1);
                float p2 = __shfl_xor_sync(0xFFFFFFFFu, v2, 1);
                float p3 = __shfl_xor_sync(0xFFFFFFFFu, v3, 1);
                float gi, gf, gg, go;
                if (!half) { gi = v0; gf = v1; gg = p0; go = p1; }
                else       { gi = p2; gf = p3; gg = v2; go = v3; }
                long m = mBase + wm * 64 + mt * 16 + r4 + (half ? 8 : 0);
                if (MODE == 3) {
                    float4 xq = *(const float4*)&Cadd[m * (long)FOURH + 4 * (long)j];
                    gi += xq.x; gf += xq.y; gg += xq.z; go += xq.w;
                }
                gi += bi; gf += bf; gg += bg; go += bo;
                float cin = (MODE == 0) ? cIO[m * HID + j] : cIn2[m * HID + j];
                float cc = sigm(gf) * cin + sigm(gi) * tanhf(gg);
                float h = sigm(go) * tanhf(cc);
                cIO[m * HID + j] = cc;
                if (MODE == 0) hOutH[m * HID + j] = __float2half(h);
                else           hOutF[m * HID + j] = h;
            }
        }
    }
}

// ------------------------------------------------- fused one-time prep ------
// All converts/splits/zero/detect in ONE launch (so launch #2.. are GEMMs).
#define P0 ((long)BB*2048)        /* cond cvt */
#define P1 ((long)FOURH*CONDD)    /* w1ih split (interleave) */
#define P2 ((long)FOURH*HID)      /* w1hh split (interleave, off CONDD) */
#define P3 ((long)MID*HID)        /* condW split */
#define P4 ((long)FOURH*320)      /* w2ih split (interleave) */
#define P5 ((long)FOURH*HID)      /* w2hh split (interleave) */
#define P6 ((long)BB*OPD)         /* operators cvt */
#define P7 ((long)BB*EXD)         /* extras cvt */
#define P8 ((long)BB*HID)         /* zero h1a/c1 */
#define PREP_TOTAL (P0+P1+P2+P3+P4+P5+P6+P7+P8)

__device__ __forceinline__ void splitv(float v, __half& h, __half& l) {
    h = __float2half(v);
    l = __float2half(v - __half2float(h));
}

__global__ void prep_k(const float* __restrict__ conds,
                       const float* __restrict__ w1ih, const float* __restrict__ w1hh,
                       const float* __restrict__ condW, const float* __restrict__ w2ih,
                       const float* __restrict__ w2hh,
                       const float* __restrict__ ops, const float* __restrict__ exs,
                       const int* __restrict__ m32)
{
    long idx = (long)blockIdx.x * blockDim.x + threadIdx.x;
    if (idx == 0) {
        int all0 = 1;
        for (int i = 1; i < 64; i += 2) all0 &= (m32[i] == 0);
        g_map64 = all0;
    }
    if (idx < P0) { g_cond16[idx] = __float2half(conds[idx]); return; }
    idx -= P0;
    if (idx < P1) {
        long r = idx / CONDD; int c = (int)(idx - r * CONDD);
        long dr = ((r & 511) << 2) + (r >> 9);
        __half h, l; splitv(w1ih[idx], h, l);
        g_w1h[dr * 768 + c] = h; g_w1l[dr * 768 + c] = l; return;
    }
    idx -= P1;
    if (idx < P2) {
        long r = idx / HID; int c = (int)(idx - r * HID);
        long dr = ((r & 511) << 2) + (r >> 9);
        __half h, l; splitv(w1hh[idx], h, l);
        g_w1h[dr * 768 + CONDD + c] = h; g_w1l[dr * 768 + CONDD + c] = l; return;
    }
    idx -= P2;
    if (idx < P3) {
        __half h, l; splitv(condW[idx], h, l);
        g_cwh[idx] = h; g_cwl[idx] = l; return;
    }
    idx -= P3;
    if (idx < P4) {
        long r = idx / 320; int c = (int)(idx - r * 320);
        long dr = ((r & 511) << 2) + (r >> 9);
        __half h, l; splitv(w2ih[idx], h, l);
        g_w2ih[dr * 320 + c] = h; g_w2il[dr * 320 + c] = l; return;
    }
    idx -= P4;
    if (idx < P5) {
        long r = idx / HID; int c = (int)(idx - r * HID);
        long dr = ((r & 511) << 2) + (r >> 9);
        __half h, l; splitv(w2hh[idx], h, l);
        g_w2hh[dr * HID + c] = h; g_w2hl[dr * HID + c] = l; return;
    }
    idx -= P5;
    if (idx < P6) {
        long r = idx / OPD; int c = (int)(idx - r * OPD);
        g_opex16[r * 64 + c] = __float2half(ops[idx]); return;
    }
    idx -= P6;
    if (idx < P7) {
        long r = idx / EXD; int c = (int)(idx - r * EXD);
        g_opex16[r * 64 + OPD + c] = __float2half(exs[idx]); return;
    }
    idx -= P7;
    if (idx < P8) {
        g_h1a[idx] = __float2half(0.f);
        g_c1[idx] = 0.f;
    }
}

// ----------------------------------------------------------- elementwise ----
__global__ void tcell0_k(const float* __restrict__ xpl, const float* __restrict__ bhh,
                         float* __restrict__ h, float* __restrict__ c)
{
    int idx = blockIdx.x * blockDim.x + threadIdx.x;  // NN*HID
    int m = idx >> 9, j = idx & 511;
    float4 q = *(const float4*)&xpl[(long)m * FOURH + 4 * j];  // interleaved i,f,g,o
    float i_ = sigm(q.x + bhh[j]);
    float gg = tanhf(q.z + bhh[1024 + j]);
    float o_ = sigm(q.w + bhh[1536 + j]);
    float cc = i_ * gg;
    c[idx] = cc;
    h[idx] = o_ * tanhf(cc);
}

__global__ void gatherT_k(const void* __restrict__ mapping, int level,
                          const float* __restrict__ h, const float* __restrict__ c,
                          __half* __restrict__ hb, float* __restrict__ cb)
{
    int idx = blockIdx.x * blockDim.x + threadIdx.x;  // NN*HID
    int n = idx >> 9, j = idx & 511;
    long flat = ((long)level * NN + n) * 2;
    int m0, m1;
    if (g_map64) {
        m0 = (int)((const long long*)mapping)[flat];
        m1 = (int)((const long long*)mapping)[flat + 1];
    } else {
        m0 = ((const int*)mapping)[flat];
        m1 = ((const int*)mapping)[flat + 1];
    }
    float hv = 0.f, cv = 0.f;
    if (m0 > 0) { hv += h[(long)(m0-1)*HID + j]; cv += c[(long)(m0-1)*HID + j]; }
    if (m1 > 0) { hv += h[(long)(m1-1)*HID + j]; cv += c[(long)(m1-1)*HID + j]; }
    hb[idx] = __float2half(0.5f * hv);
    cb[idx] = 0.5f * cv;
}

// ---------------------------------------------------------------- batchnorm -
__global__ void bn_part_k(const float* __restrict__ x, int M, int N, double* __restrict__ acc)
{
    int rows = (M + gridDim.x - 1) / gridDim.x;
    int r0 = blockIdx.x * rows;
    int r1 = min(M, r0 + rows);
    for (int col = threadIdx.x; col < N; col += blockDim.x) {
        double s = 0.0, s2 = 0.0;
        for (int r = r0; r < r1; r++) {
            float v = x[(long)r * N + col];
            s += v; s2 += (double)v * v;
        }
        atomicAdd(&acc[col], s);
        atomicAdd(&acc[N + col], s2);
    }
}

__global__ void bn_fin_k(const double* __restrict__ acc, int M, int N,
                         float* __restrict__ mu, float* __restrict__ rs)
{
    int j = blockIdx.x * blockDim.x + threadIdx.x;
    if (j < N) {
        double m = acc[j] / M;
        double var = acc[N + j] / M - m * m;
        mu[j] = (float)m;
        rs[j] = rsqrtf((float)var + 1e-5f);
    }
}

__global__ void bn_apply_h_k(const float* __restrict__ x, const float* __restrict__ mu,
                             const float* __restrict__ rs, const float* __restrict__ gm_,
                             const float* __restrict__ bt, __half* __restrict__ y, int M, int N)
{
    long idx = (long)blockIdx.x * blockDim.x + threadIdx.x;
    if (idx < (long)M * N) {
        int j = idx % N;
        y[idx] = __float2half(gm_[j] * (x[idx] - mu[j]) * rs[j] + bt[j]);
    }
}

__global__ void bn_apply_k(const float* __restrict__ x, const float* __restrict__ mu,
                           const float* __restrict__ rs, const float* __restrict__ gm_,
                           const float* __restrict__ bt, float* __restrict__ y, int M, int N)
{
    int idx = blockIdx.x * blockDim.x + threadIdx.x;
    if (idx < M * N) {
        int j = idx % N;
        y[idx] = gm_[j] * (x[idx] - mu[j]) * rs[j] + bt[j];
    }
}

// ------------------------------------------------------------ orchestration -
extern "C" void kernel_launch(void* const* d_in, const int* in_sizes, int n_in,
                              void* d_out, int out_size)
{
    const float* operators = (const float*)d_in[0];
    const float* extras    = (const float*)d_in[1];
    const float* conds     = (const float*)d_in[2];
    const void*  mapping   =               d_in[4];
    const float* w1ih = (const float*)d_in[5];
    const float* w1hh = (const float*)d_in[6];
    const float* b1ih = (const float*)d_in[7];
    const float* b1hh = (const float*)d_in[8];
    const float* condW = (const float*)d_in[9];
    const float* condb = (const float*)d_in[10];
    const float* bn1g = (const float*)d_in[11];
    const float* bn1b = (const float*)d_in[12];
    const float* w2ih = (const float*)d_in[13];
    const float* w2hh = (const float*)d_in[14];
    const float* b2ih = (const float*)d_in[15];
    const float* b2hh = (const float*)d_in[16];
    const float* bn2g = (const float*)d_in[17];
    const float* bn2b = (const float*)d_in[18];
    float* out = (float*)d_out;

    cudaFuncSetAttribute(gemm_k<0>, cudaFuncAttributeMaxDynamicSharedMemorySize, SMEM_TOT);
    cudaFuncSetAttribute(gemm_k<1>, cudaFuncAttributeMaxDynamicSharedMemorySize, SMEM_TOT);
    cudaFuncSetAttribute(gemm_k<2>, cudaFuncAttributeMaxDynamicSharedMemorySize, SMEM_TOT);
    cudaFuncSetAttribute(gemm_k<3>, cudaFuncAttributeMaxDynamicSharedMemorySize, SMEM_TOT);

    __half *cond16, *h1a, *h1b, *last16, *opex16, *hb16;
    __half *w1h, *w1l, *cwh, *cwl, *w2ihh, *w2ihl, *w2hhh, *w2hhl;
    float *c1, *last, *xp2, *h2, *c2, *cb, *mu, *rs;
    double* bnacc;
    cudaGetSymbolAddress((void**)&cond16, g_cond16);
    cudaGetSymbolAddress((void**)&h1a, g_h1a);
    cudaGetSymbolAddress((void**)&h1b, g_h1b);
    cudaGetSymbolAddress((void**)&c1, g_c1);
    cudaGetSymbolAddress((void**)&last, g_last);
    cudaGetSymbolAddress((void**)&last16, g_last16);
    cudaGetSymbolAddress((void**)&opex16, g_opex16);
    cudaGetSymbolAddress((void**)&xp2, g_xp2);
    cudaGetSymbolAddress((void**)&h2, g_h2);
    cudaGetSymbolAddress((void**)&c2, g_c2);
    cudaGetSymbolAddress((void**)&hb16, g_hb16);
    cudaGetSymbolAddress((void**)&cb, g_cb);
    cudaGetSymbolAddress((void**)&w1h, g_w1h);
    cudaGetSymbolAddress((void**)&w1l, g_w1l);
    cudaGetSymbolAddress((void**)&cwh, g_cwh);
    cudaGetSymbolAddress((void**)&cwl, g_cwl);
    cudaGetSymbolAddress((void**)&w2ihh, g_w2ih);
    cudaGetSymbolAddress((void**)&w2ihl, g_w2il);
    cudaGetSymbolAddress((void**)&w2hhh, g_w2hh);
    cudaGetSymbolAddress((void**)&w2hhl, g_w2hl);
    cudaGetSymbolAddress((void**)&bnacc, g_bnacc);
    cudaGetSymbolAddress((void**)&mu, g_mu);
    cudaGetSymbolAddress((void**)&rs, g_rs);

    // ---- launch 1: ALL one-time prep fused (converts, splits, zero, detect)
    prep_k<<<(unsigned)((PREP_TOTAL + 255) / 256), 256>>>(
        conds, w1ih, w1hh, condW, w2ih, w2hh, operators, extras, (const int*)mapping);

    // ---- launches 2-9: lstm1 fused GEMM+cell (ncu -s 5 -c 1 lands on #6)
    // x-part (K<256) single product; W1hh region (K>=256) split hi+lo.
    __half* hcur = h1a;
    __half* hnxt = h1b;
    for (int t = 0; t < TT; t++) {
        gemm_k<0><<<dim3(FOURH/128, BB/128), 256, SMEM_TOT>>>(
            cond16 + t*CONDD, 2048, CONDD,
            hcur, HID,
            w1h, w1l, CONDD,
            b1ih, b1hh, (const float*)0,
            c1, (const float*)0, hnxt, (float*)0,
            FOURH, CONDD + HID);
        __half* tmp = hcur; hcur = hnxt; hnxt = tmp;
    }

    // ---- last = relu(h1 @ condW^T + condb); batchnorm1 -> f16 (single product)
    gemm_k<1><<<dim3(MID/128, BB/128), 256, SMEM_TOT>>>(
        hcur, HID, 1 << 30, hcur, HID,
        cwh, cwl, 1 << 30,
        condb, (const float*)0, (const float*)0,
        (float*)0, (const float*)0, (__half*)0, last,
        MID, HID);
    cudaMemsetAsync(bnacc, 0, sizeof(double) * 2 * MID);
    bn_part_k<<<128, 256>>>(last, BB, MID, bnacc);
    bn_fin_k<<<2, 256>>>(bnacc, BB, MID, mu, rs);
    bn_apply_h_k<<<(BB*MID)/256, 256>>>(last, mu, rs, bn1g, bn1b, last16, BB, MID);

    // ---- xp2 = [op|extra|last] @ W2ih^T + b2ih (interleaved output, single product)
    gemm_k<2><<<dim3(FOURH/128, BB/128), 256, SMEM_TOT>>>(
        opex16, 64, 64,
        last16, MID,
        w2ihh, w2ihl, 1 << 30,
        b2ih, (const float*)0, (const float*)0,
        (float*)0, (const float*)0, (__half*)0, xp2,
        FOURH, 320);

    // ---- tree LSTM (recurrent W2hh: split hi+lo)
    tcell0_k<<<(NN*HID)/256, 256>>>(xp2 + (long)(LLV-1)*NN*FOURH, b2hh, h2, c2);
    for (int lvl = LLV - 2; lvl >= 0; lvl--) {
        gatherT_k<<<(NN*HID)/256, 256>>>(mapping, lvl, h2, c2, hb16, cb);
        gemm_k<3><<<dim3(FOURH/128, NN/128), 256, SMEM_TOT>>>(
            hb16, HID, 1 << 30, hb16, HID,
            w2hhh, w2hhl, 0,
            b2hh, (const float*)0, xp2 + (long)lvl*NN*FOURH,
            c2, cb, (__half*)0, h2,
            FOURH, HID);
    }

    // ---- batchnorm2 -> out
    cudaMemsetAsync(bnacc, 0, sizeof(double) * 2 * HID);
    bn_part_k<<<16, 256>>>(h2, NN, HID, bnacc);
    bn_fin_k<<<2, 256>>>(bnacc, NN, HID, mu, rs);
    bn_apply_k<<<(NN*HID)/256, 256>>>(h2, mu, rs, bn2g, bn2b, out, NN, HID);
}

// round 13
// speedup vs baseline: 1.1636x; 1.1636x over previous
#include <cuda_runtime.h>
#include <cuda_fp16.h>
#include <math.h>
#include <stdint.h>

typedef unsigned long long ull;

#define HID   512
#define FOURH 2048
#define MID   256
#define CONDD 256
#define OPD   32
#define EXD   32
#define LLV   16
#define NN    1024
#define TT    8
#define BB    (LLV*NN)   /* 16384 */

// ---------------------------------------------------------------- scratch ---
__device__ __align__(16) __half g_cond16[(size_t)BB*2048];
__device__ __align__(16) __half g_h1a[(size_t)BB*HID];
__device__ __align__(16) __half g_h1b[(size_t)BB*HID];
__device__ __align__(16) float  g_c1[(size_t)BB*HID];
__device__ __align__(16) float  g_last[(size_t)BB*MID];
__device__ __align__(16) __half g_last16[(size_t)BB*MID];
__device__ __align__(16) __half g_opex16[(size_t)BB*64];
__device__ __align__(16) float  g_xp2[(size_t)BB*FOURH];
__device__ __align__(16) float  g_h2[NN*HID];
__device__ __align__(16) float  g_c2[NN*HID];
__device__ __align__(16) __half g_hb16[NN*HID];
__device__ __align__(16) float  g_cb[NN*HID];
__device__ __align__(16) __half g_w1h[FOURH*768];
__device__ __align__(16) __half g_w1l[FOURH*768];
__device__ __align__(16) __half g_cwh[MID*HID];
__device__ __align__(16) __half g_cwl[MID*HID];
__device__ __align__(16) __half g_w2ih[FOURH*320];
__device__ __align__(16) __half g_w2il[FOURH*320];
__device__ __align__(16) __half g_w2hh[FOURH*HID];
__device__ __align__(16) __half g_w2hl[FOURH*HID];
__device__ double g_bnacc[2*HID];
__device__ float  g_mu[HID];
__device__ float  g_rs[HID];
__device__ int    g_map64;

// ---------------------------------------------------------------- helpers ---
__device__ __forceinline__ uint32_t smem_u32(const void* p) {
    uint32_t a;
    asm("{ .reg .u64 t; cvta.to.shared.u64 t, %1; cvt.u32.u64 %0, t; }" : "=r"(a) : "l"(p));
    return a;
}
__device__ __forceinline__ void cpa16(uint32_t dst, const void* src) {
    asm volatile("cp.async.cg.shared.global [%0], [%1], 16;" :: "r"(dst), "l"(src) : "memory");
}
__device__ __forceinline__ void ldmx4(uint32_t* r, uint32_t addr) {
    asm volatile("ldmatrix.sync.aligned.m8n8.x4.shared.b16 {%0,%1,%2,%3}, [%4];"
        : "=r"(r[0]), "=r"(r[1]), "=r"(r[2]), "=r"(r[3]) : "r"(addr));
}
__device__ __forceinline__ void mma_f16(float* d, const uint32_t* a, const uint32_t* b) {
    asm volatile("mma.sync.aligned.m16n8k16.row.col.f32.f16.f16.f32 "
        "{%0,%1,%2,%3}, {%4,%5,%6,%7}, {%8,%9}, {%0,%1,%2,%3};"
        : "+f"(d[0]), "+f"(d[1]), "+f"(d[2]), "+f"(d[3])
        : "r"(a[0]), "r"(a[1]), "r"(a[2]), "r"(a[3]), "r"(b[0]), "r"(b[1]));
}
__device__ __forceinline__ float sigm(float x) { return 1.f / (1.f + expf(-x)); }

// ---------------------------------------------------------------- GEMM ------
// C[M,Nf] = A[M,0:K] @ B[Nf,0:K]^T, A fp16, B fp16 hi (+ lo product only for
// K-chunks with kc >= loFrom — the recurrent-weight region).
// sB = B row stride in elements (may exceed K: reduction over a K-prefix).
// CTA 128x128, K-chunk 64, double-buffered cp.async, 144B-padded smem rows
// (9 banks of 16B, 9r mod 8 = permutation => conflict-free ldmatrix).
// K, kSplit, loFrom must be multiples of 64.
// MODE 0: fused LSTM cell (interleaved gates), c in-place, h->f16 out
// MODE 1: relu(+bias0) -> f32 C
// MODE 2: +bias0 (perm-indexed, interleaved C) -> f32 C
// MODE 3: fused LSTM cell + Cadd(xp2), c: cIn2->cIO, h->f32 out
#define ROWB  144
#define T_BH  (128*ROWB)
#define T_BL  (2*128*ROWB)
#define STAGE (3*128*ROWB)
#define SMEM_TOT (2*STAGE)

template<int MODE>
__global__ __launch_bounds__(256, 2)
void gemm_k(const __half* __restrict__ A0, long sA0, int kSplit,
            const __half* __restrict__ A1, long sA1,
            const __half* __restrict__ Bh, const __half* __restrict__ Bl,
            long sB, int loFrom,
            const float* __restrict__ bias0, const float* __restrict__ bias1,
            const float* __restrict__ Cadd,
            float* __restrict__ cIO, const float* __restrict__ cIn2,
            __half* __restrict__ hOutH, float* __restrict__ hOutF,
            int Nf, int K)
{
    extern __shared__ __align__(128) char sm[];
    uint32_t smb = smem_u32(sm);
    int tid = threadIdx.x;
    int mBase = blockIdx.y * 128;
    int nBase = blockIdx.x * 128;

    float acc[4][4][4];
#pragma unroll
    for (int a = 0; a < 4; a++)
#pragma unroll
        for (int b = 0; b < 4; b++)
#pragma unroll
            for (int q = 0; q < 4; q++) acc[a][b][q] = 0.f;

    int NC = K >> 6;

    auto issue_stage = [&](int s, int c) {
        int kc = c << 6;
        const __half* ap; long sA; int col;
        if (kc < kSplit) { ap = A0; sA = sA0; col = kc; }
        else             { ap = A1; sA = sA1; col = kc - kSplit; }
        uint32_t stg = smb + (uint32_t)s * STAGE;
#pragma unroll
        for (int i = 0; i < 4; i++) {           // A: 128 rows x 128B
            int idx = tid + (i << 8);
            int row = idx >> 3, cc = idx & 7;
            long eo = (long)(mBase + row) * sA + col + (cc << 3);
            cpa16(stg + row * ROWB + cc * 16, ap + eo);
        }
        int lo = (kc >= loFrom);
#pragma unroll
        for (int i = 0; i < 4; i++) {           // B: 128 rows x 128B (hi [+ lo])
            int idx = tid + (i << 8);
            int row = idx >> 3, cc = idx & 7;
            long eo = (long)(nBase + row) * sB + kc + (cc << 3);
            uint32_t d = stg + row * ROWB + cc * 16;
            cpa16(d + T_BH, Bh + eo);
            if (lo) cpa16(d + T_BL, Bl + eo);
        }
        asm volatile("cp.async.commit_group;" ::: "memory");
    };

    int lane = tid & 31, wid = tid >> 5;
    int wm = wid & 1, wn = wid >> 1;
    int arow = (lane & 7) + (((lane >> 3) & 1) << 3);
    int ahalf = lane >> 4;
    int brow = ((lane >> 4) << 3) + (lane & 7);
    int bhalf = (lane >> 3) & 1;

    issue_stage(0, 0);
    for (int c = 0; c < NC; c++) {
        if (c + 1 < NC) {
            issue_stage((c + 1) & 1, c + 1);
            asm volatile("cp.async.wait_group 1;" ::: "memory");
        } else {
            asm volatile("cp.async.wait_group 0;" ::: "memory");
        }
        __syncthreads();

        uint32_t sb = smb + (uint32_t)(c & 1) * STAGE;
        int lo = ((c << 6) >= loFrom);
#pragma unroll
        for (int ks = 0; ks < 4; ks++) {        // 4 k16-steps per 64-chunk
            uint32_t a_r[4][4], b_h[4][2], b_l[4][2];
#pragma unroll
            for (int mt = 0; mt < 4; mt++) {
                uint32_t ad = sb + (uint32_t)(wm * 64 + mt * 16 + arow) * ROWB
                            + (uint32_t)(ks * 2 + ahalf) * 16;
                ldmx4(a_r[mt], ad);
            }
#pragma unroll
            for (int bp = 0; bp < 2; bp++) {
                uint32_t bd = sb + T_BH + (uint32_t)(wn * 32 + bp * 16 + brow) * ROWB
                            + (uint32_t)(ks * 2 + bhalf) * 16;
                ldmx4(&b_h[bp * 2][0], bd);
                if (lo) ldmx4(&b_l[bp * 2][0], bd + (T_BL - T_BH));
            }
            if (lo) {
#pragma unroll
                for (int mt = 0; mt < 4; mt++)
#pragma unroll
                    for (int nt = 0; nt < 4; nt++) {
                        mma_f16(acc[mt][nt], a_r[mt], b_h[nt]);
                        mma_f16(acc[mt][nt], a_r[mt], b_l[nt]);
                    }
            } else {
#pragma unroll
                for (int mt = 0; mt < 4; mt++)
#pragma unroll
                    for (int nt = 0; nt < 4; nt++)
                        mma_f16(acc[mt][nt], a_r[mt], b_h[nt]);
            }
        }
        __syncthreads();
    }

    // ---- epilogue
    if (MODE == 1 || MODE == 2) {
        int r4 = lane >> 2, c2 = (lane & 3) << 1;
#pragma unroll
        for (int mt = 0; mt < 4; mt++) {
            long m0 = mBase + wm * 64 + mt * 16 + r4;
#pragma unroll
            for (int nt = 0; nt < 4; nt++) {
                int gn = nBase + wn * 32 + nt * 8 + c2;
                int bx = (MODE == 2) ? ((gn & 3) * 512 + (gn >> 2)) : gn;
                int by = (MODE == 2) ? (((gn + 1) & 3) * 512 + ((gn + 1) >> 2)) : gn + 1;
                float b0x = bias0[bx], b0y = bias0[by];
#pragma unroll
                for (int hf = 0; hf < 2; hf++) {
                    long gm = m0 + hf * 8;
                    float vx = acc[mt][nt][hf * 2 + 0] + b0x;
                    float vy = acc[mt][nt][hf * 2 + 1] + b0y;
                    if (MODE == 1) { vx = fmaxf(vx, 0.f); vy = fmaxf(vy, 0.f); }
                    float2 v; v.x = vx; v.y = vy;
                    *(float2*)&hOutF[gm * (long)Nf + gn] = v;
                }
            }
        }
    } else {
        int half = lane & 1, r4 = lane >> 2;
#pragma unroll
        for (int nt = 0; nt < 4; nt++) {
            int j = (nBase + wn * 32 + nt * 8 + ((lane & 2) << 1)) >> 2;
            float bi = bias0[j], bf = bias0[512 + j], bg = bias0[1024 + j], bo = bias0[1536 + j];
            if (MODE == 0) {
                bi += bias1[j]; bf += bias1[512 + j];
                bg += bias1[1024 + j]; bo += bias1[1536 + j];
            }
#pragma unroll
            for (int mt = 0; mt < 4; mt++) {
                float v0 = acc[mt][nt][0], v1 = acc[mt][nt][1];
                float v2 = acc[mt][nt][2], v3 = acc[mt][nt][3];
                float p0 = __shfl_xor_sync(0xFFFFFFFFu, v0, 1);
                float p1 = __shfl_xor_sync(0xFFFFFFFFu, v1, 1);
                float p2 = __shfl_xor_sync(0xFFFFFFFFu, v2, 1);
                float p3 = __shfl_xor_sync(0xFFFFFFFFu, v3, 1);
                float gi, gf, gg, go;
                if (!half) { gi = v0; gf = v1; gg = p0; go = p1; }
                else       { gi = p2; gf = p3; gg = v2; go = v3; }
                long m = mBase + wm * 64 + mt * 16 + r4 + (half ? 8 : 0);
                if (MODE == 3) {
                    float4 xq = *(const float4*)&Cadd[m * (long)FOURH + 4 * (long)j];
                    gi += xq.x; gf += xq.y; gg += xq.z; go += xq.w;
                }
                gi += bi; gf += bf; gg += bg; go += bo;
                float cin = (MODE == 0) ? cIO[m * HID + j] : cIn2[m * HID + j];
                float cc = sigm(gf) * cin + sigm(gi) * tanhf(gg);
                float h = sigm(go) * tanhf(cc);
                cIO[m * HID + j] = cc;
                if (MODE == 0) hOutH[m * HID + j] = __float2half(h);
                else           hOutF[m * HID + j] = h;
            }
        }
    }
}

// ------------------------------------------------- fused one-time prep ------
#define P0 ((long)BB*2048)        /* cond cvt */
#define P1 ((long)FOURH*CONDD)    /* w1ih split (interleave) */
#define P2 ((long)FOURH*HID)      /* w1hh split (interleave, off CONDD) */
#define P3 ((long)MID*HID)        /* condW split */
#define P4 ((long)FOURH*320)      /* w2ih split (interleave) */
#define P5 ((long)FOURH*HID)      /* w2hh split (interleave) */
#define P6 ((long)BB*OPD)         /* operators cvt */
#define P7 ((long)BB*EXD)         /* extras cvt */
#define P8 ((long)BB*HID)         /* zero c1 */
#define PREP_TOTAL (P0+P1+P2+P3+P4+P5+P6+P7+P8)

__device__ __forceinline__ void splitv(float v, __half& h, __half& l) {
    h = __float2half(v);
    l = __float2half(v - __half2float(h));
}

__global__ void prep_k(const float* __restrict__ conds,
                       const float* __restrict__ w1ih, const float* __restrict__ w1hh,
                       const float* __restrict__ condW, const float* __restrict__ w2ih,
                       const float* __restrict__ w2hh,
                       const float* __restrict__ ops, const float* __restrict__ exs,
                       const int* __restrict__ m32)
{
    long idx = (long)blockIdx.x * blockDim.x + threadIdx.x;
    if (idx == 0) {
        int all0 = 1;
        for (int i = 1; i < 64; i += 2) all0 &= (m32[i] == 0);
        g_map64 = all0;
    }
    if (idx < P0) { g_cond16[idx] = __float2half(conds[idx]); return; }
    idx -= P0;
    if (idx < P1) {
        long r = idx / CONDD; int c = (int)(idx - r * CONDD);
        long dr = ((r & 511) << 2) + (r >> 9);
        __half h, l; splitv(w1ih[idx], h, l);
        g_w1h[dr * 768 + c] = h; g_w1l[dr * 768 + c] = l; return;
    }
    idx -= P1;
    if (idx < P2) {
        long r = idx / HID; int c = (int)(idx - r * HID);
        long dr = ((r & 511) << 2) + (r >> 9);
        __half h, l; splitv(w1hh[idx], h, l);
        g_w1h[dr * 768 + CONDD + c] = h; g_w1l[dr * 768 + CONDD + c] = l; return;
    }
    idx -= P2;
    if (idx < P3) {
        __half h, l; splitv(condW[idx], h, l);
        g_cwh[idx] = h; g_cwl[idx] = l; return;
    }
    idx -= P3;
    if (idx < P4) {
        long r = idx / 320; int c = (int)(idx - r * 320);
        long dr = ((r & 511) << 2) + (r >> 9);
        __half h, l; splitv(w2ih[idx], h, l);
        g_w2ih[dr * 320 + c] = h; g_w2il[dr * 320 + c] = l; return;
    }
    idx -= P4;
    if (idx < P5) {
        long r = idx / HID; int c = (int)(idx - r * HID);
        long dr = ((r & 511) << 2) + (r >> 9);
        __half h, l; splitv(w2hh[idx], h, l);
        g_w2hh[dr * HID + c] = h; g_w2hl[dr * HID + c] = l; return;
    }
    idx -= P5;
    if (idx < P6) {
        long r = idx / OPD; int c = (int)(idx - r * OPD);
        g_opex16[r * 64 + c] = __float2half(ops[idx]); return;
    }
    idx -= P6;
    if (idx < P7) {
        long r = idx / EXD; int c = (int)(idx - r * EXD);
        g_opex16[r * 64 + OPD + c] = __float2half(exs[idx]); return;
    }
    idx -= P7;
    if (idx < P8) g_c1[idx] = 0.f;
}

// ----------------------------------------------------------- elementwise ----
__global__ void tcell0_k(const float* __restrict__ xpl, const float* __restrict__ bhh,
                         float* __restrict__ h, float* __restrict__ c)
{
    int idx = blockIdx.x * blockDim.x + threadIdx.x;  // NN*HID
    int m = idx >> 9, j = idx & 511;
    float4 q = *(const float4*)&xpl[(long)m * FOURH + 4 * j];  // interleaved i,f,g,o
    float i_ = sigm(q.x + bhh[j]);
    float gg = tanhf(q.z + bhh[1024 + j]);
    float o_ = sigm(q.w + bhh[1536 + j]);
    float cc = i_ * gg;
    c[idx] = cc;
    h[idx] = o_ * tanhf(cc);
}

__global__ void gatherT_k(const void* __restrict__ mapping, int level,
                          const float* __restrict__ h, const float* __restrict__ c,
                          __half* __restrict__ hb, float* __restrict__ cb)
{
    int idx = blockIdx.x * blockDim.x + threadIdx.x;  // NN*HID
    int n = idx >> 9, j = idx & 511;
    long flat = ((long)level * NN + n) * 2;
    int m0, m1;
    if (g_map64) {
        m0 = (int)((const long long*)mapping)[flat];
        m1 = (int)((const long long*)mapping)[flat + 1];
    } else {
        m0 = ((const int*)mapping)[flat];
        m1 = ((const int*)mapping)[flat + 1];
    }
    float hv = 0.f, cv = 0.f;
    if (m0 > 0) { hv += h[(long)(m0-1)*HID + j]; cv += c[(long)(m0-1)*HID + j]; }
    if (m1 > 0) { hv += h[(long)(m1-1)*HID + j]; cv += c[(long)(m1-1)*HID + j]; }
    hb[idx] = __float2half(0.5f * hv);
    cb[idx] = 0.5f * cv;
}

// ---------------------------------------------------------------- batchnorm -
__global__ void bn_part_k(const float* __restrict__ x, int M, int N, double* __restrict__ acc)
{
    int rows = (M + gridDim.x - 1) / gridDim.x;
    int r0 = blockIdx.x * rows;
    int r1 = min(M, r0 + rows);
    for (int col = threadIdx.x; col < N; col += blockDim.x) {
        double s = 0.0, s2 = 0.0;
        for (int r = r0; r < r1; r++) {
            float v = x[(long)r * N + col];
            s += v; s2 += (double)v * v;
        }
        atomicAdd(&acc[col], s);
        atomicAdd(&acc[N + col], s2);
    }
}

__global__ void bn_fin_k(const double* __restrict__ acc, int M, int N,
                         float* __restrict__ mu, float* __restrict__ rs)
{
    int j = blockIdx.x * blockDim.x + threadIdx.x;
    if (j < N) {
        double m = acc[j] / M;
        double var = acc[N + j] / M - m * m;
        mu[j] = (float)m;
        rs[j] = rsqrtf((float)var + 1e-5f);
    }
}

__global__ void bn_apply_h_k(const float* __restrict__ x, const float* __restrict__ mu,
                             const float* __restrict__ rs, const float* __restrict__ gm_,
                             const float* __restrict__ bt, __half* __restrict__ y, int M, int N)
{
    long idx = (long)blockIdx.x * blockDim.x + threadIdx.x;
    if (idx < (long)M * N) {
        int j = idx % N;
        y[idx] = __float2half(gm_[j] * (x[idx] - mu[j]) * rs[j] + bt[j]);
    }
}

__global__ void bn_apply_k(const float* __restrict__ x, const float* __restrict__ mu,
                           const float* __restrict__ rs, const float* __restrict__ gm_,
                           const float* __restrict__ bt, float* __restrict__ y, int M, int N)
{
    int idx = blockIdx.x * blockDim.x + threadIdx.x;
    if (idx < M * N) {
        int j = idx % N;
        y[idx] = gm_[j] * (x[idx] - mu[j]) * rs[j] + bt[j];
    }
}

// ------------------------------------------------------------ orchestration -
extern "C" void kernel_launch(void* const* d_in, const int* in_sizes, int n_in,
                              void* d_out, int out_size)
{
    const float* operators = (const float*)d_in[0];
    const float* extras    = (const float*)d_in[1];
    const float* conds     = (const float*)d_in[2];
    const void*  mapping   =               d_in[4];
    const float* w1ih = (const float*)d_in[5];
    const float* w1hh = (const float*)d_in[6];
    const float* b1ih = (const float*)d_in[7];
    const float* b1hh = (const float*)d_in[8];
    const float* condW = (const float*)d_in[9];
    const float* condb = (const float*)d_in[10];
    const float* bn1g = (const float*)d_in[11];
    const float* bn1b = (const float*)d_in[12];
    const float* w2ih = (const float*)d_in[13];
    const float* w2hh = (const float*)d_in[14];
    const float* b2ih = (const float*)d_in[15];
    const float* b2hh = (const float*)d_in[16];
    const float* bn2g = (const float*)d_in[17];
    const float* bn2b = (const float*)d_in[18];
    float* out = (float*)d_out;

    cudaFuncSetAttribute(gemm_k<0>, cudaFuncAttributeMaxDynamicSharedMemorySize, SMEM_TOT);
    cudaFuncSetAttribute(gemm_k<1>, cudaFuncAttributeMaxDynamicSharedMemorySize, SMEM_TOT);
    cudaFuncSetAttribute(gemm_k<2>, cudaFuncAttributeMaxDynamicSharedMemorySize, SMEM_TOT);
    cudaFuncSetAttribute(gemm_k<3>, cudaFuncAttributeMaxDynamicSharedMemorySize, SMEM_TOT);

    __half *cond16, *h1a, *h1b, *last16, *opex16, *hb16;
    __half *w1h, *w1l, *cwh, *cwl, *w2ihh, *w2ihl, *w2hhh, *w2hhl;
    float *c1, *last, *xp2, *h2, *c2, *cb, *mu, *rs;
    double* bnacc;
    cudaGetSymbolAddress((void**)&cond16, g_cond16);
    cudaGetSymbolAddress((void**)&h1a, g_h1a);
    cudaGetSymbolAddress((void**)&h1b, g_h1b);
    cudaGetSymbolAddress((void**)&c1, g_c1);
    cudaGetSymbolAddress((void**)&last, g_last);
    cudaGetSymbolAddress((void**)&last16, g_last16);
    cudaGetSymbolAddress((void**)&opex16, g_opex16);
    cudaGetSymbolAddress((void**)&xp2, g_xp2);
    cudaGetSymbolAddress((void**)&h2, g_h2);
    cudaGetSymbolAddress((void**)&c2, g_c2);
    cudaGetSymbolAddress((void**)&hb16, g_hb16);
    cudaGetSymbolAddress((void**)&cb, g_cb);
    cudaGetSymbolAddress((void**)&w1h, g_w1h);
    cudaGetSymbolAddress((void**)&w1l, g_w1l);
    cudaGetSymbolAddress((void**)&cwh, g_cwh);
    cudaGetSymbolAddress((void**)&cwl, g_cwl);
    cudaGetSymbolAddress((void**)&w2ihh, g_w2ih);
    cudaGetSymbolAddress((void**)&w2ihl, g_w2il);
    cudaGetSymbolAddress((void**)&w2hhh, g_w2hh);
    cudaGetSymbolAddress((void**)&w2hhl, g_w2hl);
    cudaGetSymbolAddress((void**)&bnacc, g_bnacc);
    cudaGetSymbolAddress((void**)&mu, g_mu);
    cudaGetSymbolAddress((void**)&rs, g_rs);

    // ---- launch 1: ALL one-time prep fused (converts, splits, zero, detect)
    prep_k<<<(unsigned)((PREP_TOTAL + 255) / 256), 256>>>(
        conds, w1ih, w1hh, condW, w2ih, w2hh, operators, extras, (const int*)mapping);

    // ---- lstm1: fused GEMM+cell, h ping-pong, c in place.
    // t=0: h==0 exactly => reduce over K=256 x-prefix only (B stride stays 768).
    // t>=1: x-part (K<256) single product; W1hh region (K>=256) split hi+lo.
    __half* hcur = h1a;
    __half* hnxt = h1b;
    for (int t = 0; t < TT; t++) {
        if (t == 0) {
            gemm_k<0><<<dim3(FOURH/128, BB/128), 256, SMEM_TOT>>>(
                cond16, 2048, 1 << 30,
                (const __half*)0, 0,
                w1h, w1l, 768, 1 << 30,
                b1ih, b1hh, (const float*)0,
                c1, (const float*)0, hnxt, (float*)0,
                FOURH, CONDD);
        } else {
            gemm_k<0><<<dim3(FOURH/128, BB/128), 256, SMEM_TOT>>>(
                cond16 + t*CONDD, 2048, CONDD,
                hcur, HID,
                w1h, w1l, 768, CONDD,
                b1ih, b1hh, (const float*)0,
                c1, (const float*)0, hnxt, (float*)0,
                FOURH, CONDD + HID);
        }
        __half* tmp = hcur; hcur = hnxt; hnxt = tmp;
    }

    // ---- last = relu(h1 @ condW^T + condb); batchnorm1 -> f16 (single product)
    gemm_k<1><<<dim3(MID/128, BB/128), 256, SMEM_TOT>>>(
        hcur, HID, 1 << 30, hcur, HID,
        cwh, cwl, HID, 1 << 30,
        condb, (const float*)0, (const float*)0,
        (float*)0, (const float*)0, (__half*)0, last,
        MID, HID);
    cudaMemsetAsync(bnacc, 0, sizeof(double) * 2 * MID);
    bn_part_k<<<128, 256>>>(last, BB, MID, bnacc);
    bn_fin_k<<<2, 256>>>(bnacc, BB, MID, mu, rs);
    bn_apply_h_k<<<(BB*MID)/256, 256>>>(last, mu, rs, bn1g, bn1b, last16, BB, MID);

    // ---- xp2 = [op|extra|last] @ W2ih^T + b2ih (interleaved output, single product)
    gemm_k<2><<<dim3(FOURH/128, BB/128), 256, SMEM_TOT>>>(
        opex16, 64, 64,
        last16, MID,
        w2ihh, w2ihl, 320, 1 << 30,
        b2ih, (const float*)0, (const float*)0,
        (float*)0, (const float*)0, (__half*)0, xp2,
        FOURH, 320);

    // ---- tree LSTM (recurrent W2hh: split hi+lo)
    tcell0_k<<<(NN*HID)/256, 256>>>(xp2 + (long)(LLV-1)*NN*FOURH, b2hh, h2, c2);
    for (int lvl = LLV - 2; lvl >= 0; lvl--) {
        gatherT_k<<<(NN*HID)/256, 256>>>(mapping, lvl, h2, c2, hb16, cb);
        gemm_k<3><<<dim3(FOURH/128, NN/128), 256, SMEM_TOT>>>(
            hb16, HID, 1 << 30, hb16, HID,
            w2hhh, w2hhl, HID, 0,
            b2hh, (const float*)0, xp2 + (long)lvl*NN*FOURH,
            c2, cb, (__half*)0, h2,
            FOURH, HID);
    }

    // ---- batchnorm2 -> out
    cudaMemsetAsync(bnacc, 0, sizeof(double) * 2 * HID);
    bn_part_k<<<16, 256>>>(h2, NN, HID, bnacc);
    bn_fin_k<<<2, 256>>>(bnacc, NN, HID, mu, rs);
    bn_apply_k<<<(NN*HID)/256, 256>>>(h2, mu, rs, bn2g, bn2b, out, NN, HID);
}